// round 7
// baseline (speedup 1.0000x reference)
#include <cuda_runtime.h>
#include <math.h>

#define BB 16
#define TT 1024
#define DDIM 512
#define BT (BB*TT)
#define PER ((long)BT*DDIM)

__device__ float g_scratch[13L*PER + 16777216L + 2L*262144L];
__device__ float g_prev[2][BB*DDIM];
__device__ int   g_cnt[TT];

__device__ __forceinline__ float sigf(float x) { return 1.f / (1.f + expf(-x)); }

__global__ void init_k() {
    int tid = blockIdx.x * blockDim.x + threadIdx.x;
    if (tid < BB*DDIM) g_prev[0][tid] = 0.f;
    if (tid < TT)      g_cnt[tid] = 0;
}

// in [Z,R,C] -> out [Z,C,R]
__global__ void transpose_k(const float* __restrict__ in, float* __restrict__ out,
                            int R, int C, long sIn, long sOut) {
    __shared__ float tile[32][33];
    const float* ib = in  + (long)blockIdx.z * sIn;
    float*       ob = out + (long)blockIdx.z * sOut;
    int c0 = blockIdx.x * 32, r0 = blockIdx.y * 32;
    for (int i = threadIdx.y; i < 32; i += 8)
        tile[i][threadIdx.x] = ib[(long)(r0 + i) * C + c0 + threadIdx.x];
    __syncthreads();
    for (int i = threadIdx.y; i < 32; i += 8)
        ob[(long)(c0 + i) * R + r0 + threadIdx.x] = tile[threadIdx.x][i];
}

__global__ void softmax1024(float* __restrict__ data) {
    __shared__ float red[8];
    int tid = threadIdx.x;
    float4* p = ((float4*)data) + ((long)blockIdx.x << 8);
    float4 v = p[tid];
    float m = fmaxf(fmaxf(v.x, v.y), fmaxf(v.z, v.w));
    #pragma unroll
    for (int o = 16; o; o >>= 1) m = fmaxf(m, __shfl_xor_sync(0xffffffffu, m, o));
    if ((tid & 31) == 0) red[tid >> 5] = m;
    __syncthreads();
    m = red[0];
    #pragma unroll
    for (int i = 1; i < 8; i++) m = fmaxf(m, red[i]);
    v.x = __expf(v.x - m); v.y = __expf(v.y - m);
    v.z = __expf(v.z - m); v.w = __expf(v.w - m);
    float s = v.x + v.y + v.z + v.w;
    #pragma unroll
    for (int o = 16; o; o >>= 1) s += __shfl_xor_sync(0xffffffffu, s, o);
    __syncthreads();
    if ((tid & 31) == 0) red[tid >> 5] = s;
    __syncthreads();
    s = red[0];
    #pragma unroll
    for (int i = 1; i < 8; i++) s += red[i];
    float inv = 1.f / s;
    v.x *= inv; v.y *= inv; v.z *= inv; v.w *= inv;
    p[tid] = v;
}

// NT SGEMM: C = epi(scale * A@Bw^T + bias). Tiles 128x128x16, 256 thr, 8x8 micro.
// EPI: 0 none 1 silu 2 sigmoid 3 sig(x)*aux1 4 silu(x+aux1) 5 sig(x)*aux1+(1-sig)*aux2
template<int EPI>
__global__ __launch_bounds__(256, 2)
void sgemm(const float* __restrict__ A, const float* __restrict__ Bw,
           const float* __restrict__ bias,
           const float* __restrict__ aux1, const float* __restrict__ aux2,
           float* __restrict__ C,
           int K, int ldb, int N, long sA, long sB, long sC, float scale)
{
    __shared__ float As[16][128];
    __shared__ float Bs[16][128];
    const int tid = threadIdx.x;
    const float* Ab = A  + (long)blockIdx.z * sA + (long)blockIdx.y * 128 * K;
    const float* Bb = Bw + (long)blockIdx.z * sB + (long)blockIdx.x * 128 * ldb;

    float acc[8][8];
    #pragma unroll
    for (int i = 0; i < 8; i++)
        #pragma unroll
        for (int j = 0; j < 8; j++) acc[i][j] = 0.f;

    const int cx = tid & 15, cy = tid >> 4;
    const int m0 = cy * 8, n0 = cx * 8;
    const int r0 = tid >> 2, r1 = r0 + 64;
    const int kc = (tid & 3) << 2;

    for (int kt = 0; kt < K; kt += 16) {
        float4 ra0 = *(const float4*)&Ab[(long)r0 * K   + kt + kc];
        float4 ra1 = *(const float4*)&Ab[(long)r1 * K   + kt + kc];
        float4 rb0 = *(const float4*)&Bb[(long)r0 * ldb + kt + kc];
        float4 rb1 = *(const float4*)&Bb[(long)r1 * ldb + kt + kc];
        __syncthreads();
        As[kc+0][r0]=ra0.x; As[kc+1][r0]=ra0.y; As[kc+2][r0]=ra0.z; As[kc+3][r0]=ra0.w;
        As[kc+0][r1]=ra1.x; As[kc+1][r1]=ra1.y; As[kc+2][r1]=ra1.z; As[kc+3][r1]=ra1.w;
        Bs[kc+0][r0]=rb0.x; Bs[kc+1][r0]=rb0.y; Bs[kc+2][r0]=rb0.z; Bs[kc+3][r0]=rb0.w;
        Bs[kc+0][r1]=rb1.x; Bs[kc+1][r1]=rb1.y; Bs[kc+2][r1]=rb1.z; Bs[kc+3][r1]=rb1.w;
        __syncthreads();
        #pragma unroll
        for (int kk = 0; kk < 16; kk++) {
            float av[8], bv[8];
            *(float4*)&av[0] = *(const float4*)&As[kk][m0];
            *(float4*)&av[4] = *(const float4*)&As[kk][m0 + 4];
            *(float4*)&bv[0] = *(const float4*)&Bs[kk][n0];
            *(float4*)&bv[4] = *(const float4*)&Bs[kk][n0 + 4];
            #pragma unroll
            for (int i = 0; i < 8; i++)
                #pragma unroll
                for (int j = 0; j < 8; j++)
                    acc[i][j] += av[i] * bv[j];
        }
    }

    const int gn0 = blockIdx.x * 128 + n0;
    float bs[8];
    #pragma unroll
    for (int j = 0; j < 8; j++) bs[j] = bias ? bias[gn0 + j] : 0.f;

    #pragma unroll
    for (int i = 0; i < 8; i++) {
        long gm = (long)blockIdx.y * 128 + m0 + i;
        long cidx = (long)blockIdx.z * sC + gm * N + gn0;
        float o[8];
        #pragma unroll
        for (int j = 0; j < 8; j++) {
            float x = acc[i][j] * scale + bs[j];
            if (EPI == 0)      o[j] = x;
            else if (EPI == 1) o[j] = x * sigf(x);
            else if (EPI == 2) o[j] = sigf(x);
            else if (EPI == 3) o[j] = sigf(x) * aux1[cidx + j];
            else if (EPI == 4) { float y = x + aux1[cidx + j]; o[j] = y * sigf(y); }
            else { float s_ = sigf(x); o[j] = s_ * aux1[cidx + j] + (1.f - s_) * aux2[cidx + j]; }
        }
        *(float4*)&C[cidx]     = *(float4*)&o[0];
        *(float4*)&C[cidx + 4] = *(float4*)&o[4];
    }
}

// EMA recurrence: 128 persistent CTAs x 256 thr, CTA owns 4 d-rows.
__global__ __launch_bounds__(256, 1)
void ema_rec(const float* __restrict__ bin, const float* __restrict__ pa,
             const float* __restrict__ pd, const float* __restrict__ Wa,
             const float* __restrict__ Wd, float* __restrict__ ema)
{
    extern __shared__ float sm[];
    float* w_s    = sm;                // [8][512]: rows 0-3 Wa, 4-7 Wd
    float* prev_s = sm + 4096;         // [16][512]
    float* dot_s  = sm + 4096 + 8192;  // [8][16]
    const int tid = threadIdx.x;
    const int j0  = blockIdx.x * 4;

    for (int i = tid; i < 2048; i += 256) {
        int r = i >> 9, d = i & 511;
        w_s[r * 512 + d]       = Wa[(long)(j0 + r) * 1024 + d];
        w_s[(4 + r) * 512 + d] = Wd[(long)(j0 + r) * 1024 + d];
    }

    const int lane = tid & 31, warp = tid >> 5;
    const int rg = (warp & 1) * 4;
    const int bg = (warp >> 1) * 4;
    const int er = tid >> 4, eb = tid & 15;
    float4* prev4 = (float4*)prev_s;

    for (int t = 0; t < TT; t++) {
        float bt_v = 0.f, pa_v = 0.f, pd_v = 0.f;
        if (tid < 64) {
            long off = ((long)eb * TT + t) * DDIM + j0 + er;
            bt_v = bin[off]; pa_v = pa[off]; pd_v = pd[off];
        }
        const float4* pg = (const float4*)g_prev[t & 1];
        #pragma unroll
        for (int i = 0; i < 8; i++) prev4[tid + i * 256] = pg[tid + i * 256];
        __syncthreads();

        float acc[4][4];
        #pragma unroll
        for (int i = 0; i < 4; i++)
            #pragma unroll
            for (int j = 0; j < 4; j++) acc[i][j] = 0.f;

        #pragma unroll
        for (int dd = 0; dd < 16; dd++) {
            int d = lane + (dd << 5);
            float w0 = w_s[(rg+0)*512+d], w1 = w_s[(rg+1)*512+d];
            float w2 = w_s[(rg+2)*512+d], w3 = w_s[(rg+3)*512+d];
            float p0 = prev_s[(bg+0)*512+d], p1 = prev_s[(bg+1)*512+d];
            float p2 = prev_s[(bg+2)*512+d], p3 = prev_s[(bg+3)*512+d];
            acc[0][0]+=w0*p0; acc[0][1]+=w0*p1; acc[0][2]+=w0*p2; acc[0][3]+=w0*p3;
            acc[1][0]+=w1*p0; acc[1][1]+=w1*p1; acc[1][2]+=w1*p2; acc[1][3]+=w1*p3;
            acc[2][0]+=w2*p0; acc[2][1]+=w2*p1; acc[2][2]+=w2*p2; acc[2][3]+=w2*p3;
            acc[3][0]+=w3*p0; acc[3][1]+=w3*p1; acc[3][2]+=w3*p2; acc[3][3]+=w3*p3;
        }
        #pragma unroll
        for (int i = 0; i < 4; i++)
            #pragma unroll
            for (int j = 0; j < 4; j++) {
                float v = acc[i][j];
                #pragma unroll
                for (int o = 16; o; o >>= 1) v += __shfl_xor_sync(0xffffffffu, v, o);
                acc[i][j] = v;
            }
        if (lane == 0) {
            #pragma unroll
            for (int i = 0; i < 4; i++)
                #pragma unroll
                for (int j = 0; j < 4; j++)
                    dot_s[(rg + i) * 16 + bg + j] = acc[i][j];
        }
        __syncthreads();

        if (tid < 64) {
            float alpha = tanhf(dot_s[er * 16 + eb] + pa_v);
            float delta = tanhf(dot_s[(4 + er) * 16 + eb] + pd_v);
            float p = prev_s[eb * 512 + j0 + er];
            float x = alpha * bt_v + (1.f - alpha * delta) * p;
            float e = 1.f / (1.f + expf(-x));
            g_prev[(t + 1) & 1][eb * 512 + j0 + er] = e;
            ema[((long)eb * TT + t) * DDIM + j0 + er] = e;
        }
        __syncthreads();
        if (tid == 0) {
            __threadfence();
            atomicAdd(&g_cnt[t], 1);
            volatile int* c = &g_cnt[t];
            while (*c < 128) { }
            __threadfence();
        }
        __syncthreads();
    }
}

extern "C" void kernel_launch(void* const* d_in, const int* in_sizes, int n_in,
                              void* d_out, int out_size) {
    const float* b    = (const float*)d_in[0];
    const float* Wq   = (const float*)d_in[1];
    const float* bq   = (const float*)d_in[2];
    const float* Wk   = (const float*)d_in[3];
    const float* bk   = (const float*)d_in[4];
    const float* Wv   = (const float*)d_in[5];
    const float* bv   = (const float*)d_in[6];
    const float* Wa   = (const float*)d_in[7];
    const float* ba   = (const float*)d_in[8];
    const float* Wd   = (const float*)d_in[9];
    const float* bd   = (const float*)d_in[10];
    const float* Wout = (const float*)d_in[11];
    const float* bout = (const float*)d_in[12];
    const float* W_f  = (const float*)d_in[13];
    const float* b_f  = (const float*)d_in[14];
    const float* W_ec = (const float*)d_in[15];
    const float* W_zc = (const float*)d_in[16];
    const float* b_C  = (const float*)d_in[17];
    const float* W_i  = (const float*)d_in[18];
    const float* b_i  = (const float*)d_in[19];
    const float* W_o  = (const float*)d_in[20];
    const float* b_o  = (const float*)d_in[21];
    float* out = (float*)d_out;

    float* S = nullptr;
    cudaGetSymbolAddress((void**)&S, g_scratch);
    float* pre_a  = S + 0 * PER;
    float* pre_d  = S + 1 * PER;
    float* ema    = S + 2 * PER;
    float* bema   = S + 3 * PER;
    float* q      = S + 4 * PER;
    float* kmat   = S + 5 * PER;
    float* v      = S + 6 * PER;
    float* vT     = S + 7 * PER;
    float* z      = S + 8 * PER;
    float* zf     = S + 9 * PER;
    float* tmpc   = S + 10 * PER;
    float* zc     = S + 11 * PER;
    float* bh     = S + 12 * PER;
    float* scores = S + 13 * PER;
    float* wT1    = scores + 16777216L;
    float* wT2    = wT1 + 262144L;

    cudaFuncSetAttribute(ema_rec, cudaFuncAttributeMaxDynamicSharedMemorySize, 49664);

    const dim3 blk(256);
    const dim3 gD(4, 128, 1);
    const long sBT = (long)TT * DDIM;
    const long sTT = (long)TT * TT;
    const float iscale = 1.f / sqrtf(512.f);

    init_k<<<32, 256>>>();
    transpose_k<<<dim3(16, 16, 1), dim3(32, 8)>>>(W_ec, wT1, 512, 512, 0, 0);
    transpose_k<<<dim3(16, 16, 1), dim3(32, 8)>>>(W_zc, wT2, 512, 512, 0, 0);

    sgemm<0><<<gD, blk>>>(b, Wa + 512, ba, nullptr, nullptr, pre_a, 512, 1024, 512, 0, 0, 0, 1.f);
    sgemm<0><<<gD, blk>>>(b, Wd + 512, bd, nullptr, nullptr, pre_d, 512, 1024, 512, 0, 0, 0, 1.f);

    ema_rec<<<128, 256, 49664>>>(b, pre_a, pre_d, Wa, Wd, ema);

    sgemm<1><<<gD, blk>>>(ema, Wout, bout, nullptr, nullptr, bema, 512, 512, 512, 0, 0, 0, 1.f);

    sgemm<0><<<gD, blk>>>(bema, Wq, bq, nullptr, nullptr, q,    512, 512, 512, 0, 0, 0, 1.f);
    sgemm<0><<<gD, blk>>>(bema, Wk, bk, nullptr, nullptr, kmat, 512, 512, 512, 0, 0, 0, 1.f);
    sgemm<0><<<gD, blk>>>(bema, Wv, bv, nullptr, nullptr, v,    512, 512, 512, 0, 0, 0, 1.f);

    // scores[b] = q[b] @ k[b]^T * 1/sqrt(D)
    sgemm<0><<<dim3(8, 8, 16), blk>>>(q, kmat, nullptr, nullptr, nullptr, scores,
                                      512, 512, 1024, sBT, sBT, sTT, iscale);
    softmax1024<<<BT, 256>>>(scores);

    // vT[b] = v[b]^T  ([1024,512] -> [512,1024])
    transpose_k<<<dim3(16, 32, 16), dim3(32, 8)>>>(v, vT, 1024, 512, sBT, sBT);

    // z[b] = attn[b] @ v[b]
    sgemm<0><<<dim3(4, 8, 16), blk>>>(scores, vT, nullptr, nullptr, nullptr, z,
                                      1024, 1024, 512, sTT, sBT, sBT, 1.f);

    // zf = sigmoid(bema@W_f^T + b_f) * z
    sgemm<3><<<gD, blk>>>(bema, W_f, b_f, z, nullptr, zf, 512, 512, 512, 0, 0, 0, 1.f);
    // tmpc = bema @ W_EMA_c
    sgemm<0><<<gD, blk>>>(bema, wT1, nullptr, nullptr, nullptr, tmpc, 512, 512, 512, 0, 0, 0, 1.f);
    // zc = silu(zf @ W_z_C + b_C + tmpc)
    sgemm<4><<<gD, blk>>>(zf, wT2, b_C, tmpc, nullptr, zc, 512, 512, 512, 0, 0, 0, 1.f);
    // bh = i*zc + (1-i)*b, i = sigmoid(bema@W_i^T + b_i)
    sgemm<5><<<gD, blk>>>(bema, W_i, b_i, zc, b, bh, 512, 512, 512, 0, 0, 0, 1.f);
    // out = sigmoid(bh@W_o^T + b_o)
    sgemm<2><<<gD, blk>>>(bh, W_o, b_o, nullptr, nullptr, out, 512, 512, 512, 0, 0, 0, 1.f);
}

// round 8
// speedup vs baseline: 1.5248x; 1.5248x over previous
#include <cuda_runtime.h>
#include <math.h>

#define BB 16
#define TT 1024
#define DDIM 512
#define BT (BB*TT)
#define PER ((long)BT*DDIM)

__device__ float g_scratch[13L*PER + 16777216L + 2L*262144L];
__device__ float g_prev[2][BB*DDIM];
__device__ int   g_cnt[TT];

__device__ __forceinline__ float sigf(float x) { return 1.f / (1.f + expf(-x)); }
__device__ __forceinline__ unsigned tf32(float x) {
    unsigned u; asm("cvt.rna.tf32.f32 %0, %1;" : "=r"(u) : "f"(x)); return u;
}

__global__ void init_k() {
    int tid = blockIdx.x * blockDim.x + threadIdx.x;
    if (tid < BB*DDIM) g_prev[0][tid] = 0.f;
    if (tid < TT)      g_cnt[tid] = 0;
}

// in [Z,R,C] -> out [Z,C,R]
__global__ void transpose_k(const float* __restrict__ in, float* __restrict__ out,
                            int R, int C, long sIn, long sOut) {
    __shared__ float tile[32][33];
    const float* ib = in  + (long)blockIdx.z * sIn;
    float*       ob = out + (long)blockIdx.z * sOut;
    int c0 = blockIdx.x * 32, r0 = blockIdx.y * 32;
    for (int i = threadIdx.y; i < 32; i += 8)
        tile[i][threadIdx.x] = ib[(long)(r0 + i) * C + c0 + threadIdx.x];
    __syncthreads();
    for (int i = threadIdx.y; i < 32; i += 8)
        ob[(long)(c0 + i) * R + r0 + threadIdx.x] = tile[threadIdx.x][i];
}

__global__ void softmax1024(float* __restrict__ data) {
    __shared__ float red[8];
    int tid = threadIdx.x;
    float4* p = ((float4*)data) + ((long)blockIdx.x << 8);
    float4 v = p[tid];
    float m = fmaxf(fmaxf(v.x, v.y), fmaxf(v.z, v.w));
    #pragma unroll
    for (int o = 16; o; o >>= 1) m = fmaxf(m, __shfl_xor_sync(0xffffffffu, m, o));
    if ((tid & 31) == 0) red[tid >> 5] = m;
    __syncthreads();
    m = red[0];
    #pragma unroll
    for (int i = 1; i < 8; i++) m = fmaxf(m, red[i]);
    v.x = __expf(v.x - m); v.y = __expf(v.y - m);
    v.z = __expf(v.z - m); v.w = __expf(v.w - m);
    float s = v.x + v.y + v.z + v.w;
    #pragma unroll
    for (int o = 16; o; o >>= 1) s += __shfl_xor_sync(0xffffffffu, s, o);
    __syncthreads();
    if ((tid & 31) == 0) red[tid >> 5] = s;
    __syncthreads();
    s = red[0];
    #pragma unroll
    for (int i = 1; i < 8; i++) s += red[i];
    float inv = 1.f / s;
    v.x *= inv; v.y *= inv; v.z *= inv; v.w *= inv;
    p[tid] = v;
}

// ---------------------------------------------------------------------------
// tf32 tensor-core NT GEMM: C = epi(scale * A@Bw^T + bias)
// Tiles 128x128x16, 256 thr (8 warps: 2m x 4n, warp tile 64x32), double buffer.
// smem stride 136 -> fragment LDS conflict-free (bank = (8k+m) mod 32).
// EPI: 0 none 1 silu 2 sigmoid 3 sig(x)*aux1 4 silu(x+aux1) 5 lerp(aux2,aux1,sig)
// ---------------------------------------------------------------------------
template<int EPI>
__global__ __launch_bounds__(256)
void tgemm(const float* __restrict__ A, const float* __restrict__ Bw,
           const float* __restrict__ bias,
           const float* __restrict__ aux1, const float* __restrict__ aux2,
           float* __restrict__ C,
           int K, int ldb, int N, long sA, long sB, long sC, float scale)
{
    __shared__ float As[2][16][136];
    __shared__ float Bs[2][16][136];
    const int tid  = threadIdx.x;
    const int lane = tid & 31, warp = tid >> 5;
    const int wm = warp >> 2, wn = warp & 3;          // 2 x 4 warp grid
    const int g = lane >> 2, t = lane & 3;
    const float* Ab = A  + (long)blockIdx.z * sA + (long)blockIdx.y * 128 * K;
    const float* Bb = Bw + (long)blockIdx.z * sB + (long)blockIdx.x * 128 * ldb;
    const int r0 = tid >> 2, r1 = r0 + 64;
    const int kc = (tid & 3) << 2;

    float acc[4][4][4];
    #pragma unroll
    for (int i = 0; i < 4; i++)
        #pragma unroll
        for (int j = 0; j < 4; j++)
            #pragma unroll
            for (int q = 0; q < 4; q++) acc[i][j][q] = 0.f;

    unsigned va[8], vb[8];

    auto LD = [&](int kt) {
        float4 ra0 = *(const float4*)&Ab[(long)r0 * K   + kt + kc];
        float4 ra1 = *(const float4*)&Ab[(long)r1 * K   + kt + kc];
        float4 rb0 = *(const float4*)&Bb[(long)r0 * ldb + kt + kc];
        float4 rb1 = *(const float4*)&Bb[(long)r1 * ldb + kt + kc];
        va[0]=tf32(ra0.x); va[1]=tf32(ra0.y); va[2]=tf32(ra0.z); va[3]=tf32(ra0.w);
        va[4]=tf32(ra1.x); va[5]=tf32(ra1.y); va[6]=tf32(ra1.z); va[7]=tf32(ra1.w);
        vb[0]=tf32(rb0.x); vb[1]=tf32(rb0.y); vb[2]=tf32(rb0.z); vb[3]=tf32(rb0.w);
        vb[4]=tf32(rb1.x); vb[5]=tf32(rb1.y); vb[6]=tf32(rb1.z); vb[7]=tf32(rb1.w);
    };
    auto ST = [&](int buf) {
        #pragma unroll
        for (int i = 0; i < 4; i++) {
            As[buf][kc+i][r0] = __uint_as_float(va[i]);
            As[buf][kc+i][r1] = __uint_as_float(va[4+i]);
            Bs[buf][kc+i][r0] = __uint_as_float(vb[i]);
            Bs[buf][kc+i][r1] = __uint_as_float(vb[4+i]);
        }
    };
    auto MM = [&](int buf) {
        #pragma unroll
        for (int c = 0; c < 2; c++) {
            const int k0 = c * 8 + t;
            unsigned af[4][4], bf[4][2];
            #pragma unroll
            for (int i = 0; i < 4; i++) {
                int m = wm * 64 + i * 16 + g;
                af[i][0] = __float_as_uint(As[buf][k0][m]);
                af[i][1] = __float_as_uint(As[buf][k0][m + 8]);
                af[i][2] = __float_as_uint(As[buf][k0 + 4][m]);
                af[i][3] = __float_as_uint(As[buf][k0 + 4][m + 8]);
            }
            #pragma unroll
            for (int j = 0; j < 4; j++) {
                int n = wn * 32 + j * 8 + g;
                bf[j][0] = __float_as_uint(Bs[buf][k0][n]);
                bf[j][1] = __float_as_uint(Bs[buf][k0 + 4][n]);
            }
            #pragma unroll
            for (int i = 0; i < 4; i++)
                #pragma unroll
                for (int j = 0; j < 4; j++)
                    asm volatile(
                        "mma.sync.aligned.m16n8k8.row.col.f32.tf32.tf32.f32 "
                        "{%0,%1,%2,%3}, {%4,%5,%6,%7}, {%8,%9}, {%0,%1,%2,%3};\n"
                        : "+f"(acc[i][j][0]), "+f"(acc[i][j][1]),
                          "+f"(acc[i][j][2]), "+f"(acc[i][j][3])
                        : "r"(af[i][0]), "r"(af[i][1]), "r"(af[i][2]), "r"(af[i][3]),
                          "r"(bf[j][0]), "r"(bf[j][1]));
        }
    };

    LD(0); ST(0); __syncthreads();
    int buf = 0;
    for (int kt = 16; kt < K; kt += 16) {
        LD(kt);
        MM(buf);
        ST(buf ^ 1);
        __syncthreads();
        buf ^= 1;
    }
    MM(buf);

    const int gn_base = blockIdx.x * 128 + wn * 32;
    #pragma unroll
    for (int i = 0; i < 4; i++) {
        const long m = (long)blockIdx.y * 128 + wm * 64 + i * 16 + g;
        #pragma unroll
        for (int j = 0; j < 4; j++) {
            const int n0 = gn_base + j * 8 + 2 * t;
            const float b0 = bias ? bias[n0]     : 0.f;
            const float b1 = bias ? bias[n0 + 1] : 0.f;
            const long i0 = (long)blockIdx.z * sC + m * N + n0;
            const long i2 = i0 + 8L * N;
            float x[4] = { acc[i][j][0] * scale + b0, acc[i][j][1] * scale + b1,
                           acc[i][j][2] * scale + b0, acc[i][j][3] * scale + b1 };
            const long idx[4] = { i0, i0 + 1, i2, i2 + 1 };
            float o[4];
            #pragma unroll
            for (int q = 0; q < 4; q++) {
                float xv = x[q];
                if (EPI == 0)      o[q] = xv;
                else if (EPI == 1) o[q] = xv * sigf(xv);
                else if (EPI == 2) o[q] = sigf(xv);
                else if (EPI == 3) o[q] = sigf(xv) * aux1[idx[q]];
                else if (EPI == 4) { float y = xv + aux1[idx[q]]; o[q] = y * sigf(y); }
                else { float s_ = sigf(xv); o[q] = s_ * aux1[idx[q]] + (1.f - s_) * aux2[idx[q]]; }
            }
            float2 w0 = { o[0], o[1] }, w1 = { o[2], o[3] };
            *(float2*)&C[i0] = w0;
            *(float2*)&C[i2] = w1;
        }
    }
}

// ---------------------------------------------------------------------------
// EMA recurrence: 128 persistent CTAs x 256 thr, CTA owns 4 d-rows.
// Loop-invariant weight rows cached in registers (64 regs/thread).
// ---------------------------------------------------------------------------
__global__ __launch_bounds__(256, 1)
void ema_rec(const float* __restrict__ bin, const float* __restrict__ pa,
             const float* __restrict__ pd, const float* __restrict__ Wa,
             const float* __restrict__ Wd, float* __restrict__ ema)
{
    __shared__ float prev_s[16 * 512];   // 32 KB
    __shared__ float dot_s[8 * 16];
    const int tid  = threadIdx.x;
    const int lane = tid & 31, warp = tid >> 5;
    const int j0 = blockIdx.x * 4;
    const int rg = (warp & 1) * 4;       // 0: alpha rows, 4: delta rows
    const int bg = (warp >> 1) * 4;      // batch group
    const int er = tid >> 4, eb = tid & 15;
    float4* prev4 = (float4*)prev_s;

    // cache weight rows in registers: w[i][dd] = Wsel[j0+i][dd*32+lane]
    const float* Wsel = (warp & 1) ? Wd : Wa;
    float wreg[4][16];
    #pragma unroll
    for (int i = 0; i < 4; i++)
        #pragma unroll
        for (int dd = 0; dd < 16; dd++)
            wreg[i][dd] = Wsel[(long)(j0 + i) * 1024 + (dd << 5) + lane];

    for (int t = 0; t < TT; t++) {
        float bt_v = 0.f, pa_v = 0.f, pd_v = 0.f;
        if (tid < 64) {
            long off = ((long)eb * TT + t) * DDIM + j0 + er;
            bt_v = bin[off]; pa_v = pa[off]; pd_v = pd[off];
        }
        const float4* pg = (const float4*)g_prev[t & 1];
        #pragma unroll
        for (int i = 0; i < 8; i++) prev4[tid + i * 256] = pg[tid + i * 256];
        __syncthreads();

        float acc[4][4];
        #pragma unroll
        for (int i = 0; i < 4; i++)
            #pragma unroll
            for (int j = 0; j < 4; j++) acc[i][j] = 0.f;

        #pragma unroll
        for (int dd = 0; dd < 16; dd++) {
            const int d = (dd << 5) + lane;
            float p0 = prev_s[(bg+0)*512+d], p1 = prev_s[(bg+1)*512+d];
            float p2 = prev_s[(bg+2)*512+d], p3 = prev_s[(bg+3)*512+d];
            #pragma unroll
            for (int i = 0; i < 4; i++) {
                float w = wreg[i][dd];
                acc[i][0] += w * p0; acc[i][1] += w * p1;
                acc[i][2] += w * p2; acc[i][3] += w * p3;
            }
        }
        #pragma unroll
        for (int i = 0; i < 4; i++)
            #pragma unroll
            for (int j = 0; j < 4; j++) {
                float v = acc[i][j];
                #pragma unroll
                for (int o = 16; o; o >>= 1) v += __shfl_xor_sync(0xffffffffu, v, o);
                acc[i][j] = v;
            }
        if (lane == 0) {
            #pragma unroll
            for (int i = 0; i < 4; i++)
                #pragma unroll
                for (int j = 0; j < 4; j++)
                    dot_s[(rg + i) * 16 + bg + j] = acc[i][j];
        }
        __syncthreads();

        if (tid < 64) {
            float alpha = tanhf(dot_s[er * 16 + eb] + pa_v);
            float delta = tanhf(dot_s[(4 + er) * 16 + eb] + pd_v);
            float p = prev_s[eb * 512 + j0 + er];
            float x = alpha * bt_v + (1.f - alpha * delta) * p;
            float e = 1.f / (1.f + expf(-x));
            g_prev[(t + 1) & 1][eb * 512 + j0 + er] = e;
            ema[((long)eb * TT + t) * DDIM + j0 + er] = e;
        }
        __syncthreads();
        if (tid == 0) {
            __threadfence();
            atomicAdd(&g_cnt[t], 1);
            volatile int* c = &g_cnt[t];
            while (*c < 128) { }
            __threadfence();   // gpu-scope: flushes L1 so next g_prev read is fresh
        }
        __syncthreads();
    }
}

extern "C" void kernel_launch(void* const* d_in, const int* in_sizes, int n_in,
                              void* d_out, int out_size) {
    const float* b    = (const float*)d_in[0];
    const float* Wq   = (const float*)d_in[1];
    const float* bq   = (const float*)d_in[2];
    const float* Wk   = (const float*)d_in[3];
    const float* bk   = (const float*)d_in[4];
    const float* Wv   = (const float*)d_in[5];
    const float* bv   = (const float*)d_in[6];
    const float* Wa   = (const float*)d_in[7];
    const float* ba   = (const float*)d_in[8];
    const float* Wd   = (const float*)d_in[9];
    const float* bd   = (const float*)d_in[10];
    const float* Wout = (const float*)d_in[11];
    const float* bout = (const float*)d_in[12];
    const float* W_f  = (const float*)d_in[13];
    const float* b_f  = (const float*)d_in[14];
    const float* W_ec = (const float*)d_in[15];
    const float* W_zc = (const float*)d_in[16];
    const float* b_C  = (const float*)d_in[17];
    const float* W_i  = (const float*)d_in[18];
    const float* b_i  = (const float*)d_in[19];
    const float* W_o  = (const float*)d_in[20];
    const float* b_o  = (const float*)d_in[21];
    float* out = (float*)d_out;

    float* S = nullptr;
    cudaGetSymbolAddress((void**)&S, g_scratch);
    float* pre_a  = S + 0 * PER;
    float* pre_d  = S + 1 * PER;
    float* ema    = S + 2 * PER;
    float* bema   = S + 3 * PER;
    float* q      = S + 4 * PER;
    float* kmat   = S + 5 * PER;
    float* v      = S + 6 * PER;
    float* vT     = S + 7 * PER;
    float* z      = S + 8 * PER;
    float* zf     = S + 9 * PER;
    float* tmpc   = S + 10 * PER;
    float* zc     = S + 11 * PER;
    float* bh     = S + 12 * PER;
    float* scores = S + 13 * PER;
    float* wT1    = scores + 16777216L;
    float* wT2    = wT1 + 262144L;

    const dim3 blk(256);
    const dim3 gD(4, 128, 1);
    const long sBT = (long)TT * DDIM;
    const long sTT = (long)TT * TT;
    const float iscale = 1.f / sqrtf(512.f);

    init_k<<<32, 256>>>();
    transpose_k<<<dim3(16, 16, 1), dim3(32, 8)>>>(W_ec, wT1, 512, 512, 0, 0);
    transpose_k<<<dim3(16, 16, 1), dim3(32, 8)>>>(W_zc, wT2, 512, 512, 0, 0);

    tgemm<0><<<gD, blk>>>(b, Wa + 512, ba, nullptr, nullptr, pre_a, 512, 1024, 512, 0, 0, 0, 1.f);
    tgemm<0><<<gD, blk>>>(b, Wd + 512, bd, nullptr, nullptr, pre_d, 512, 1024, 512, 0, 0, 0, 1.f);

    ema_rec<<<128, 256>>>(b, pre_a, pre_d, Wa, Wd, ema);

    tgemm<1><<<gD, blk>>>(ema, Wout, bout, nullptr, nullptr, bema, 512, 512, 512, 0, 0, 0, 1.f);

    tgemm<0><<<gD, blk>>>(bema, Wq, bq, nullptr, nullptr, q,    512, 512, 512, 0, 0, 0, 1.f);
    tgemm<0><<<gD, blk>>>(bema, Wk, bk, nullptr, nullptr, kmat, 512, 512, 512, 0, 0, 0, 1.f);
    tgemm<0><<<gD, blk>>>(bema, Wv, bv, nullptr, nullptr, v,    512, 512, 512, 0, 0, 0, 1.f);

    // scores[b] = q[b] @ k[b]^T / sqrt(D)
    tgemm<0><<<dim3(8, 8, 16), blk>>>(q, kmat, nullptr, nullptr, nullptr, scores,
                                      512, 512, 1024, sBT, sBT, sTT, iscale);
    softmax1024<<<BT, 256>>>(scores);

    // vT[b] = v[b]^T
    transpose_k<<<dim3(16, 32, 16), dim3(32, 8)>>>(v, vT, 1024, 512, sBT, sBT);

    // z[b] = attn[b] @ v[b]
    tgemm<0><<<dim3(4, 8, 16), blk>>>(scores, vT, nullptr, nullptr, nullptr, z,
                                      1024, 1024, 512, sTT, sBT, sBT, 1.f);

    // zf = sigmoid(bema@W_f^T + b_f) * z
    tgemm<3><<<gD, blk>>>(bema, W_f, b_f, z, nullptr, zf, 512, 512, 512, 0, 0, 0, 1.f);
    // tmpc = bema @ W_EMA_c
    tgemm<0><<<gD, blk>>>(bema, wT1, nullptr, nullptr, nullptr, tmpc, 512, 512, 512, 0, 0, 0, 1.f);
    // zc = silu(zf @ W_z_C + b_C + tmpc)
    tgemm<4><<<gD, blk>>>(zf, wT2, b_C, tmpc, nullptr, zc, 512, 512, 512, 0, 0, 0, 1.f);
    // bh = i*zc + (1-i)*b
    tgemm<5><<<gD, blk>>>(bema, W_i, b_i, zc, b, bh, 512, 512, 512, 0, 0, 0, 1.f);
    // out = sigmoid(bh@W_o^T + b_o)
    tgemm<2><<<gD, blk>>>(bh, W_o, b_o, nullptr, nullptr, out, 512, 512, 512, 0, 0, 0, 1.f);
}

// round 9
// speedup vs baseline: 1.7603x; 1.1544x over previous
#include <cuda_runtime.h>
#include <math.h>

#define BB 16
#define TT 1024
#define DDIM 512
#define BT (BB*TT)
#define PER ((long)BT*DDIM)

__device__ float g_scratch[13L*PER + 16777216L + 2L*262144L];
__device__ float g_prev[2][BB*DDIM];
__device__ int   g_cnt[TT + 1];

__device__ __forceinline__ float sigf(float x) { return 1.f / (1.f + expf(-x)); }
__device__ __forceinline__ unsigned tf32(float x) {
    unsigned u; asm("cvt.rna.tf32.f32 %0, %1;" : "=r"(u) : "f"(x)); return u;
}
__device__ __forceinline__ int ldacq(const int* p) {
    int v; asm volatile("ld.acquire.gpu.global.b32 %0, [%1];" : "=r"(v) : "l"(p) : "memory");
    return v;
}
__device__ __forceinline__ void redrel(int* p) {
    asm volatile("red.release.gpu.global.add.s32 [%0], 1;" :: "l"(p) : "memory");
}

__global__ void init_k() {
    int tid = blockIdx.x * blockDim.x + threadIdx.x;
    if (tid < BB*DDIM) g_prev[0][tid] = 0.f;
    if (tid < TT + 1)  g_cnt[tid] = 0;
}

// in [Z,R,C] -> out [Z,C,R]
__global__ void transpose_k(const float* __restrict__ in, float* __restrict__ out,
                            int R, int C, long sIn, long sOut) {
    __shared__ float tile[32][33];
    const float* ib = in  + (long)blockIdx.z * sIn;
    float*       ob = out + (long)blockIdx.z * sOut;
    int c0 = blockIdx.x * 32, r0 = blockIdx.y * 32;
    for (int i = threadIdx.y; i < 32; i += 8)
        tile[i][threadIdx.x] = ib[(long)(r0 + i) * C + c0 + threadIdx.x];
    __syncthreads();
    for (int i = threadIdx.y; i < 32; i += 8)
        ob[(long)(c0 + i) * R + r0 + threadIdx.x] = tile[threadIdx.x][i];
}

__global__ void softmax1024(float* __restrict__ data) {
    __shared__ float red[8];
    int tid = threadIdx.x;
    float4* p = ((float4*)data) + ((long)blockIdx.x << 8);
    float4 v = p[tid];
    float m = fmaxf(fmaxf(v.x, v.y), fmaxf(v.z, v.w));
    #pragma unroll
    for (int o = 16; o; o >>= 1) m = fmaxf(m, __shfl_xor_sync(0xffffffffu, m, o));
    if ((tid & 31) == 0) red[tid >> 5] = m;
    __syncthreads();
    m = red[0];
    #pragma unroll
    for (int i = 1; i < 8; i++) m = fmaxf(m, red[i]);
    v.x = __expf(v.x - m); v.y = __expf(v.y - m);
    v.z = __expf(v.z - m); v.w = __expf(v.w - m);
    float s = v.x + v.y + v.z + v.w;
    #pragma unroll
    for (int o = 16; o; o >>= 1) s += __shfl_xor_sync(0xffffffffu, s, o);
    __syncthreads();
    if ((tid & 31) == 0) red[tid >> 5] = s;
    __syncthreads();
    s = red[0];
    #pragma unroll
    for (int i = 1; i < 8; i++) s += red[i];
    float inv = 1.f / s;
    v.x *= inv; v.y *= inv; v.z *= inv; v.w *= inv;
    p[tid] = v;
}

// ---------------------------------------------------------------------------
// tf32 tensor-core NT GEMM: C = epi(scale * A@Bw^T + bias)
// Tiles 128x128x16, 256 thr, double buffer. XOR swizzle on the m/n column:
//   element (k, m) lives at As[k][ m ^ (((k>>2)&3)<<3) ]  -> stores AND
//   fragment loads both conflict-free.
// EPI: 0 none 1 silu 2 sigmoid 3 sig(x)*aux1 4 silu(x+aux1) 5 lerp(aux2,aux1,sig)
// ---------------------------------------------------------------------------
template<int EPI>
__global__ __launch_bounds__(256)
void tgemm(const float* __restrict__ A, const float* __restrict__ Bw,
           const float* __restrict__ bias,
           const float* __restrict__ aux1, const float* __restrict__ aux2,
           float* __restrict__ C,
           int K, int ldb, int N, long sA, long sB, long sC, float scale)
{
    __shared__ float As[2][16][136];
    __shared__ float Bs[2][16][136];
    const int tid  = threadIdx.x;
    const int lane = tid & 31, warp = tid >> 5;
    const int wm = warp >> 2, wn = warp & 3;
    const int g = lane >> 2, t = lane & 3;
    const float* Ab = A  + (long)blockIdx.z * sA + (long)blockIdx.y * 128 * K;
    const float* Bb = Bw + (long)blockIdx.z * sB + (long)blockIdx.x * 128 * ldb;
    const int r0 = tid >> 2, r1 = r0 + 64;
    const int kc = (tid & 3) << 2;
    const int sw = (tid & 3) << 3;       // store swizzle = q<<3
    const int r0s = r0 ^ sw, r1s = r1 ^ sw;

    float acc[4][4][4];
    #pragma unroll
    for (int i = 0; i < 4; i++)
        #pragma unroll
        for (int j = 0; j < 4; j++)
            #pragma unroll
            for (int q = 0; q < 4; q++) acc[i][j][q] = 0.f;

    unsigned va[8], vb[8];

    auto LD = [&](int kt) {
        float4 ra0 = *(const float4*)&Ab[(long)r0 * K   + kt + kc];
        float4 ra1 = *(const float4*)&Ab[(long)r1 * K   + kt + kc];
        float4 rb0 = *(const float4*)&Bb[(long)r0 * ldb + kt + kc];
        float4 rb1 = *(const float4*)&Bb[(long)r1 * ldb + kt + kc];
        va[0]=tf32(ra0.x); va[1]=tf32(ra0.y); va[2]=tf32(ra0.z); va[3]=tf32(ra0.w);
        va[4]=tf32(ra1.x); va[5]=tf32(ra1.y); va[6]=tf32(ra1.z); va[7]=tf32(ra1.w);
        vb[0]=tf32(rb0.x); vb[1]=tf32(rb0.y); vb[2]=tf32(rb0.z); vb[3]=tf32(rb0.w);
        vb[4]=tf32(rb1.x); vb[5]=tf32(rb1.y); vb[6]=tf32(rb1.z); vb[7]=tf32(rb1.w);
    };
    auto ST = [&](int buf) {
        #pragma unroll
        for (int i = 0; i < 4; i++) {
            As[buf][kc+i][r0s] = __uint_as_float(va[i]);
            As[buf][kc+i][r1s] = __uint_as_float(va[4+i]);
            Bs[buf][kc+i][r0s] = __uint_as_float(vb[i]);
            Bs[buf][kc+i][r1s] = __uint_as_float(vb[4+i]);
        }
    };
    auto MM = [&](int buf) {
        #pragma unroll
        for (int c = 0; c < 2; c++) {
            const int k0 = c * 8 + t;
            const int s0 = 16 * c, s1 = 16 * c + 8;   // load swizzles for k0, k0+4
            unsigned af[4][4], bf[4][2];
            #pragma unroll
            for (int i = 0; i < 4; i++) {
                int m = wm * 64 + i * 16 + g;
                af[i][0] = __float_as_uint(As[buf][k0    ][ m      ^ s0]);
                af[i][1] = __float_as_uint(As[buf][k0    ][(m + 8) ^ s0]);
                af[i][2] = __float_as_uint(As[buf][k0 + 4][ m      ^ s1]);
                af[i][3] = __float_as_uint(As[buf][k0 + 4][(m + 8) ^ s1]);
            }
            #pragma unroll
            for (int j = 0; j < 4; j++) {
                int n = wn * 32 + j * 8 + g;
                bf[j][0] = __float_as_uint(Bs[buf][k0    ][n ^ s0]);
                bf[j][1] = __float_as_uint(Bs[buf][k0 + 4][n ^ s1]);
            }
            #pragma unroll
            for (int i = 0; i < 4; i++)
                #pragma unroll
                for (int j = 0; j < 4; j++)
                    asm volatile(
                        "mma.sync.aligned.m16n8k8.row.col.f32.tf32.tf32.f32 "
                        "{%0,%1,%2,%3}, {%4,%5,%6,%7}, {%8,%9}, {%0,%1,%2,%3};\n"
                        : "+f"(acc[i][j][0]), "+f"(acc[i][j][1]),
                          "+f"(acc[i][j][2]), "+f"(acc[i][j][3])
                        : "r"(af[i][0]), "r"(af[i][1]), "r"(af[i][2]), "r"(af[i][3]),
                          "r"(bf[j][0]), "r"(bf[j][1]));
        }
    };

    LD(0); ST(0); __syncthreads();
    int buf = 0;
    for (int kt = 16; kt < K; kt += 16) {
        LD(kt);
        MM(buf);
        ST(buf ^ 1);
        __syncthreads();
        buf ^= 1;
    }
    MM(buf);

    const int gn_base = blockIdx.x * 128 + wn * 32;
    #pragma unroll
    for (int i = 0; i < 4; i++) {
        const long m = (long)blockIdx.y * 128 + wm * 64 + i * 16 + g;
        #pragma unroll
        for (int j = 0; j < 4; j++) {
            const int n0 = gn_base + j * 8 + 2 * t;
            const float b0 = bias ? bias[n0]     : 0.f;
            const float b1 = bias ? bias[n0 + 1] : 0.f;
            const long i0 = (long)blockIdx.z * sC + m * N + n0;
            const long i2 = i0 + 8L * N;
            float x[4] = { acc[i][j][0] * scale + b0, acc[i][j][1] * scale + b1,
                           acc[i][j][2] * scale + b0, acc[i][j][3] * scale + b1 };
            const long idx[4] = { i0, i0 + 1, i2, i2 + 1 };
            float o[4];
            #pragma unroll
            for (int q = 0; q < 4; q++) {
                float xv = x[q];
                if (EPI == 0)      o[q] = xv;
                else if (EPI == 1) o[q] = xv * sigf(xv);
                else if (EPI == 2) o[q] = sigf(xv);
                else if (EPI == 3) o[q] = sigf(xv) * aux1[idx[q]];
                else if (EPI == 4) { float y = xv + aux1[idx[q]]; o[q] = y * sigf(y); }
                else { float s_ = sigf(xv); o[q] = s_ * aux1[idx[q]] + (1.f - s_) * aux2[idx[q]]; }
            }
            float2 w0 = { o[0], o[1] }, w1 = { o[2], o[3] };
            *(float2*)&C[i0] = w0;
            *(float2*)&C[i2] = w1;
        }
    }
}

// ---------------------------------------------------------------------------
// EMA recurrence: 128 persistent CTAs x 256 thr, CTA owns 4 d-rows.
// release/acquire flag barrier (no threadfence / L1 flush); state broadcast
// via __ldcv (L1-bypass) so no invalidate is needed.
// ---------------------------------------------------------------------------
__global__ __launch_bounds__(256, 1)
void ema_rec(const float* __restrict__ bin, const float* __restrict__ pa,
             const float* __restrict__ pd, const float* __restrict__ Wa,
             const float* __restrict__ Wd, float* __restrict__ ema)
{
    __shared__ float prev_s[16 * 512];
    __shared__ float dot_s[8 * 16];
    const int tid  = threadIdx.x;
    const int lane = tid & 31, warp = tid >> 5;
    const int j0 = blockIdx.x * 4;
    const int rg = (warp & 1) * 4;
    const int bg = (warp >> 1) * 4;
    const int er = tid >> 4, eb = tid & 15;
    float4* prev4 = (float4*)prev_s;

    const float* Wsel = (warp & 1) ? Wd : Wa;
    float wreg[4][16];
    #pragma unroll
    for (int i = 0; i < 4; i++)
        #pragma unroll
        for (int dd = 0; dd < 16; dd++)
            wreg[i][dd] = Wsel[(long)(j0 + i) * 1024 + (dd << 5) + lane];

    for (int t = 0; t < TT; t++) {
        float bt_v = 0.f, pa_v = 0.f, pd_v = 0.f;
        if (tid < 64) {
            long off = ((long)eb * TT + t) * DDIM + j0 + er;
            bt_v = bin[off]; pa_v = pa[off]; pd_v = pd[off];
        }
        if (t) {
            if (tid == 0) { while (ldacq(&g_cnt[t]) < 128) { } }
            __syncthreads();
        }
        const float4* pg = (const float4*)g_prev[t & 1];
        #pragma unroll
        for (int i = 0; i < 8; i++)
            prev4[tid + i * 256] = __ldcv(pg + tid + i * 256);
        __syncthreads();

        float acc[4][4];
        #pragma unroll
        for (int i = 0; i < 4; i++)
            #pragma unroll
            for (int j = 0; j < 4; j++) acc[i][j] = 0.f;

        #pragma unroll
        for (int dd = 0; dd < 16; dd++) {
            const int d = (dd << 5) + lane;
            float p0 = prev_s[(bg+0)*512+d], p1 = prev_s[(bg+1)*512+d];
            float p2 = prev_s[(bg+2)*512+d], p3 = prev_s[(bg+3)*512+d];
            #pragma unroll
            for (int i = 0; i < 4; i++) {
                float w = wreg[i][dd];
                acc[i][0] += w * p0; acc[i][1] += w * p1;
                acc[i][2] += w * p2; acc[i][3] += w * p3;
            }
        }
        #pragma unroll
        for (int i = 0; i < 4; i++)
            #pragma unroll
            for (int j = 0; j < 4; j++) {
                float v = acc[i][j];
                #pragma unroll
                for (int o = 16; o; o >>= 1) v += __shfl_xor_sync(0xffffffffu, v, o);
                acc[i][j] = v;
            }
        if (lane == 0) {
            #pragma unroll
            for (int i = 0; i < 4; i++)
                #pragma unroll
                for (int j = 0; j < 4; j++)
                    dot_s[(rg + i) * 16 + bg + j] = acc[i][j];
        }
        __syncthreads();

        if (tid < 64) {
            float alpha = tanhf(dot_s[er * 16 + eb] + pa_v);
            float delta = tanhf(dot_s[(4 + er) * 16 + eb] + pd_v);
            float p = prev_s[eb * 512 + j0 + er];
            float x = alpha * bt_v + (1.f - alpha * delta) * p;
            float e = 1.f / (1.f + expf(-x));
            g_prev[(t + 1) & 1][eb * 512 + j0 + er] = e;
            ema[((long)eb * TT + t) * DDIM + j0 + er] = e;
        }
        __syncthreads();
        if (tid == 0) redrel(&g_cnt[t + 1]);   // release: orders prior STGs
    }
}

extern "C" void kernel_launch(void* const* d_in, const int* in_sizes, int n_in,
                              void* d_out, int out_size) {
    const float* b    = (const float*)d_in[0];
    const float* Wq   = (const float*)d_in[1];
    const float* bq   = (const float*)d_in[2];
    const float* Wk   = (const float*)d_in[3];
    const float* bk   = (const float*)d_in[4];
    const float* Wv   = (const float*)d_in[5];
    const float* bv   = (const float*)d_in[6];
    const float* Wa   = (const float*)d_in[7];
    const float* ba   = (const float*)d_in[8];
    const float* Wd   = (const float*)d_in[9];
    const float* bd   = (const float*)d_in[10];
    const float* Wout = (const float*)d_in[11];
    const float* bout = (const float*)d_in[12];
    const float* W_f  = (const float*)d_in[13];
    const float* b_f  = (const float*)d_in[14];
    const float* W_ec = (const float*)d_in[15];
    const float* W_zc = (const float*)d_in[16];
    const float* b_C  = (const float*)d_in[17];
    const float* W_i  = (const float*)d_in[18];
    const float* b_i  = (const float*)d_in[19];
    const float* W_o  = (const float*)d_in[20];
    const float* b_o  = (const float*)d_in[21];
    float* out = (float*)d_out;

    float* S = nullptr;
    cudaGetSymbolAddress((void**)&S, g_scratch);
    float* pre_a  = S + 0 * PER;
    float* pre_d  = S + 1 * PER;
    float* ema    = S + 2 * PER;
    float* bema   = S + 3 * PER;
    float* q      = S + 4 * PER;
    float* kmat   = S + 5 * PER;
    float* v      = S + 6 * PER;
    float* vT     = S + 7 * PER;
    float* z      = S + 8 * PER;
    float* zf     = S + 9 * PER;
    float* tmpc   = S + 10 * PER;
    float* zc     = S + 11 * PER;
    float* bh     = S + 12 * PER;
    float* scores = S + 13 * PER;
    float* wT1    = scores + 16777216L;
    float* wT2    = wT1 + 262144L;

    const dim3 blk(256);
    const dim3 gD(4, 128, 1);
    const long sBT = (long)TT * DDIM;
    const long sTT = (long)TT * TT;
    const float iscale = 1.f / sqrtf(512.f);

    init_k<<<32, 256>>>();
    transpose_k<<<dim3(16, 16, 1), dim3(32, 8)>>>(W_ec, wT1, 512, 512, 0, 0);
    transpose_k<<<dim3(16, 16, 1), dim3(32, 8)>>>(W_zc, wT2, 512, 512, 0, 0);

    tgemm<0><<<gD, blk>>>(b, Wa + 512, ba, nullptr, nullptr, pre_a, 512, 1024, 512, 0, 0, 0, 1.f);
    tgemm<0><<<gD, blk>>>(b, Wd + 512, bd, nullptr, nullptr, pre_d, 512, 1024, 512, 0, 0, 0, 1.f);

    ema_rec<<<128, 256>>>(b, pre_a, pre_d, Wa, Wd, ema);

    tgemm<1><<<gD, blk>>>(ema, Wout, bout, nullptr, nullptr, bema, 512, 512, 512, 0, 0, 0, 1.f);

    tgemm<0><<<gD, blk>>>(bema, Wq, bq, nullptr, nullptr, q,    512, 512, 512, 0, 0, 0, 1.f);
    tgemm<0><<<gD, blk>>>(bema, Wk, bk, nullptr, nullptr, kmat, 512, 512, 512, 0, 0, 0, 1.f);
    tgemm<0><<<gD, blk>>>(bema, Wv, bv, nullptr, nullptr, v,    512, 512, 512, 0, 0, 0, 1.f);

    tgemm<0><<<dim3(8, 8, 16), blk>>>(q, kmat, nullptr, nullptr, nullptr, scores,
                                      512, 512, 1024, sBT, sBT, sTT, iscale);
    softmax1024<<<BT, 256>>>(scores);

    transpose_k<<<dim3(16, 32, 16), dim3(32, 8)>>>(v, vT, 1024, 512, sBT, sBT);

    tgemm<0><<<dim3(4, 8, 16), blk>>>(scores, vT, nullptr, nullptr, nullptr, z,
                                      1024, 1024, 512, sTT, sBT, sBT, 1.f);

    tgemm<3><<<gD, blk>>>(bema, W_f, b_f, z, nullptr, zf, 512, 512, 512, 0, 0, 0, 1.f);
    tgemm<0><<<gD, blk>>>(bema, wT1, nullptr, nullptr, nullptr, tmpc, 512, 512, 512, 0, 0, 0, 1.f);
    tgemm<4><<<gD, blk>>>(zf, wT2, b_C, tmpc, nullptr, zc, 512, 512, 512, 0, 0, 0, 1.f);
    tgemm<5><<<gD, blk>>>(bema, W_i, b_i, zc, b, bh, 512, 512, 512, 0, 0, 0, 1.f);
    tgemm<2><<<gD, blk>>>(bh, W_o, b_o, nullptr, nullptr, out, 512, 512, 512, 0, 0, 0, 1.f);
}